// round 1
// baseline (speedup 1.0000x reference)
#include <cuda_runtime.h>
#include <cuda_bf16.h>

// Problem sizes (fixed by the reference):
//   x  [T=4, B=8, N=1024, Cin=512]  -> M = T*B*N = 32768 rows, K = 512
//   W1 [512, 512]  (out, in)  -> h = x @ W1^T
//   LIF over T (tau=2, v_th=1, hard reset 0)
//   W2 [512, 512]  -> out = s @ W2^T
#define T_STEPS 4
#define M_TOTAL 32768           // T*B*N
#define M_PER_T 8192            // B*N
#define KDIM    512
#define NDIM    512

// Scratch (no cudaMalloc allowed): h and s, 64 MB each.
__device__ float g_h[(size_t)M_TOTAL * NDIM];
__device__ float g_s[(size_t)M_TOTAL * NDIM];

// ---------------------------------------------------------------------------
// fp32 SGEMM, C[M,N] = A[M,K] * B[N,K]^T   (both inputs K-contiguous row-major)
// 128x128 block tile, BK=16, 256 threads, 8x8 per-thread microtile.
// ---------------------------------------------------------------------------
#define BM 128
#define BN 128
#define BK 16
#define TM 8
#define TN 8

__global__ void __launch_bounds__(256, 2)
sgemm_nt(const float* __restrict__ A, const float* __restrict__ B,
         float* __restrict__ C, int M, int N, int K)
{
    __shared__ float As[BK][BM];
    __shared__ float Bs[BK][BN];

    const int cRow = blockIdx.y;      // M tile
    const int cCol = blockIdx.x;      // N tile

    const int tid = threadIdx.x;
    const int tx  = tid % (BN / TN);  // 0..15
    const int ty  = tid / (BN / TN);  // 0..15

    // global->shared load mapping: each thread does 2 float4 from A, 2 from B
    const int innerRow = tid / (BK / 4);   // 0..63
    const int innerCol = tid % (BK / 4);   // 0..3

    const float* Ablk = A + (size_t)cRow * BM * K;
    const float* Bblk = B + (size_t)cCol * BN * K;

    float acc[TM][TN];
    #pragma unroll
    for (int i = 0; i < TM; ++i)
        #pragma unroll
        for (int j = 0; j < TN; ++j) acc[i][j] = 0.0f;

    float regM[TM], regN[TN];

    for (int k0 = 0; k0 < K; k0 += BK) {
        #pragma unroll
        for (int r = 0; r < BM; r += 64) {
            float4 v = *reinterpret_cast<const float4*>(
                Ablk + (size_t)(innerRow + r) * K + k0 + innerCol * 4);
            As[innerCol * 4 + 0][innerRow + r] = v.x;
            As[innerCol * 4 + 1][innerRow + r] = v.y;
            As[innerCol * 4 + 2][innerRow + r] = v.z;
            As[innerCol * 4 + 3][innerRow + r] = v.w;
        }
        #pragma unroll
        for (int r = 0; r < BN; r += 64) {
            float4 v = *reinterpret_cast<const float4*>(
                Bblk + (size_t)(innerRow + r) * K + k0 + innerCol * 4);
            Bs[innerCol * 4 + 0][innerRow + r] = v.x;
            Bs[innerCol * 4 + 1][innerRow + r] = v.y;
            Bs[innerCol * 4 + 2][innerRow + r] = v.z;
            Bs[innerCol * 4 + 3][innerRow + r] = v.w;
        }
        __syncthreads();

        #pragma unroll
        for (int k = 0; k < BK; ++k) {
            #pragma unroll
            for (int i = 0; i < TM; ++i) regM[i] = As[k][ty * TM + i];
            #pragma unroll
            for (int j = 0; j < TN; ++j) regN[j] = Bs[k][tx * TN + j];
            #pragma unroll
            for (int i = 0; i < TM; ++i)
                #pragma unroll
                for (int j = 0; j < TN; ++j)
                    acc[i][j] = fmaf(regM[i], regN[j], acc[i][j]);
        }
        __syncthreads();
    }

    float* Cblk = C + (size_t)(cRow * BM) * N + cCol * BN;
    #pragma unroll
    for (int i = 0; i < TM; ++i) {
        #pragma unroll
        for (int j = 0; j < TN; j += 4) {
            float4 v;
            v.x = acc[i][j + 0];
            v.y = acc[i][j + 1];
            v.z = acc[i][j + 2];
            v.w = acc[i][j + 3];
            *reinterpret_cast<float4*>(Cblk + (size_t)(ty * TM + i) * N + tx * TN + j) = v;
        }
    }
}

// ---------------------------------------------------------------------------
// LIF: per-channel recurrence over T=4 steps.
// Matches reference rounding exactly:
//   v = v + (x - v)/2 ;  s = (v >= 1) ;  v = s ? 0 : v
// ---------------------------------------------------------------------------
__global__ void __launch_bounds__(256)
lif_kernel(const float* __restrict__ h, float* __restrict__ s)
{
    const size_t stride = (size_t)M_PER_T * NDIM;   // elements per timestep
    size_t i = (size_t)blockIdx.x * blockDim.x + threadIdx.x;
    if (i >= stride) return;

    float v = 0.0f;
    #pragma unroll
    for (int t = 0; t < T_STEPS; ++t) {
        float x = h[t * stride + i];
        v = v + (x - v) / 2.0f;
        float spike = (v >= 1.0f) ? 1.0f : 0.0f;
        s[t * stride + i] = spike;
        if (spike != 0.0f) v = 0.0f;
    }
}

// ---------------------------------------------------------------------------
extern "C" void kernel_launch(void* const* d_in, const int* in_sizes, int n_in,
                              void* d_out, int out_size)
{
    const float* x  = (const float*)d_in[0];   // [T,B,N,Cin]
    const float* W1 = (const float*)d_in[1];   // [Cout,Cin]
    const float* W2 = (const float*)d_in[2];   // [Cout,Cout]
    float* out = (float*)d_out;                // [T,B,N,Cout]

    float *h_ptr = nullptr, *s_ptr = nullptr;
    cudaGetSymbolAddress((void**)&h_ptr, g_h);
    cudaGetSymbolAddress((void**)&s_ptr, g_s);

    dim3 grid(NDIM / BN, M_TOTAL / BM);   // (4, 256)
    dim3 block(256);

    // GEMM1: h = x @ W1^T   (exact fp32 — threshold sensitivity lives here)
    sgemm_nt<<<grid, block>>>(x, W1, h_ptr, M_TOTAL, NDIM, KDIM);

    // LIF over T
    {
        size_t n = (size_t)M_PER_T * NDIM;
        int threads = 256;
        int blocks = (int)((n + threads - 1) / threads);
        lif_kernel<<<blocks, threads>>>(h_ptr, s_ptr);
    }

    // GEMM2: out = s @ W2^T
    sgemm_nt<<<grid, block>>>(s_ptr, W2, out, M_TOTAL, NDIM, KDIM);
}

// round 4
// speedup vs baseline: 1.4445x; 1.4445x over previous
#include <cuda_runtime.h>
#include <cuda_bf16.h>
#include <cstdint>

// Shapes (fixed): x [4,8,1024,512] -> M=32768 rows, K=512; W1,W2 [512,512].
#define MTOT  32768
#define MPERT 8192
#define KD    512
#define ND    512
#define NCHAN (MPERT * ND)          // 4,194,304 channels (b*n, c)
#define FLAG_CAP 2097152

// ---------------- scratch (no cudaMalloc allowed) ----------------
__device__ __align__(16) __nv_bfloat16 g_x0[(size_t)MTOT * KD];
__device__ __align__(16) __nv_bfloat16 g_x1[(size_t)MTOT * KD];
__device__ __align__(16) __nv_bfloat16 g_w10[KD * ND];
__device__ __align__(16) __nv_bfloat16 g_w11[KD * ND];
__device__ __align__(16) __nv_bfloat16 g_w20[KD * ND];
__device__ __align__(16) __nv_bfloat16 g_w21[KD * ND];
__device__ __align__(16) float         g_h[(size_t)MTOT * ND];
__device__ __align__(16) __nv_bfloat16 g_s[(size_t)MTOT * ND];
__device__ int g_flags[FLAG_CAP];
__device__ int g_flag_count;

// ---------------- base-target PTX helpers (sm_80-era only) -----------------
__device__ __forceinline__ uint32_t smem_u32(const void* p) {
    uint32_t a;
    asm("{ .reg .u64 t; cvta.to.shared.u64 t, %1; cvt.u32.u64 %0, t; }"
        : "=r"(a) : "l"(p));
    return a;
}
__device__ __forceinline__ void cp_async16(uint32_t dst, const void* src) {
    asm volatile("cp.async.cg.shared.global [%0], [%1], 16;"
                 :: "r"(dst), "l"(src) : "memory");
}
__device__ __forceinline__ void cp_commit() {
    asm volatile("cp.async.commit_group;" ::: "memory");
}
template <int N>
__device__ __forceinline__ void cp_wait() {
    asm volatile("cp.async.wait_group %0;" :: "n"(N) : "memory");
}
__device__ __forceinline__ void ldsm_x4(uint32_t& r0, uint32_t& r1,
                                        uint32_t& r2, uint32_t& r3, uint32_t a) {
    asm volatile("ldmatrix.sync.aligned.m8n8.x4.shared.b16 {%0,%1,%2,%3}, [%4];"
                 : "=r"(r0), "=r"(r1), "=r"(r2), "=r"(r3) : "r"(a));
}
__device__ __forceinline__ void mma16816(float& c0, float& c1, float& c2, float& c3,
                                         uint32_t a0, uint32_t a1, uint32_t a2, uint32_t a3,
                                         uint32_t b0, uint32_t b1) {
    asm volatile(
        "mma.sync.aligned.m16n8k16.row.col.f32.bf16.bf16.f32 "
        "{%0,%1,%2,%3}, {%4,%5,%6,%7}, {%8,%9}, {%0,%1,%2,%3};"
        : "+f"(c0), "+f"(c1), "+f"(c2), "+f"(c3)
        : "r"(a0), "r"(a1), "r"(a2), "r"(a3), "r"(b0), "r"(b1));
}

// ---------------- bf16 HMMA GEMM: C[M,512] = sum_p A_p @ B_p^T --------------
struct GemmArgs {
    const __nv_bfloat16* A[4];
    const __nv_bfloat16* B[4];
    float* C;
    int npairs;
};

#define STAGE_BYTES 32768
#define SMEM_DYN    65536

__global__ void __launch_bounds__(256, 2) hmma_gemm(GemmArgs args)
{
    extern __shared__ char dynsmem[];
    const uint32_t sb = smem_u32(dynsmem);

    const int tid   = threadIdx.x;
    const int lane  = tid & 31;
    const int warp  = tid >> 5;
    const int wm    = warp >> 2;
    const int wn    = warp & 3;
    const int tileN = blockIdx.x;          // fast dim -> A tile L2 reuse
    const int tileM = blockIdx.y;

    const int niters = args.npairs * 8;

    const int ldRow = tid >> 1;
    const int ldC0  = (tid & 1) * 4;
    const int lrow  = lane & 15;
    const int lsel  = lane >> 4;

    float acc[4][4][4];
    #pragma unroll
    for (int i = 0; i < 4; ++i)
        #pragma unroll
        for (int j = 0; j < 4; ++j)
            #pragma unroll
            for (int q = 0; q < 4; ++q) acc[i][j][q] = 0.f;

    auto load_stage = [&](int it) {
        const int buf  = it & 1;
        const int pair = it >> 3;
        const int k0   = (it & 7) * 64;
        const __nv_bfloat16* Ap = args.A[pair] + (size_t)tileM * 128 * KD + k0;
        const __nv_bfloat16* Bp = args.B[pair] + (size_t)tileN * 128 * KD + k0;
        const uint32_t ab = sb + buf * STAGE_BYTES;
        const uint32_t bb = ab + 16384;
        const uint32_t swrow = (uint32_t)(ldRow & 7);
        #pragma unroll
        for (int c = 0; c < 4; ++c) {
            uint32_t ch = (uint32_t)(ldC0 + c);
            uint32_t sw = (ch ^ swrow) * 16u + (uint32_t)ldRow * 128u;
            cp_async16(ab + sw, Ap + (size_t)ldRow * KD + ch * 8);
            cp_async16(bb + sw, Bp + (size_t)ldRow * KD + ch * 8);
        }
        cp_commit();
    };

    load_stage(0);

    for (int it = 0; it < niters; ++it) {
        if (it + 1 < niters) load_stage(it + 1);
        else cp_commit();
        cp_wait<1>();
        __syncthreads();

        const uint32_t ab = sb + (it & 1) * STAGE_BYTES;
        const uint32_t bb = ab + 16384;

        #pragma unroll
        for (int ks = 0; ks < 4; ++ks) {
            uint32_t a[4][4];
            #pragma unroll
            for (int mt = 0; mt < 4; ++mt) {
                int row = wm * 64 + mt * 16 + lrow;
                uint32_t ch = (uint32_t)(ks * 2 + lsel);
                uint32_t ad = ab + (uint32_t)row * 128u + ((ch ^ (uint32_t)(row & 7)) * 16u);
                ldsm_x4(a[mt][0], a[mt][1], a[mt][2], a[mt][3], ad);
            }
            uint32_t b[4][2];
            #pragma unroll
            for (int nt2 = 0; nt2 < 2; ++nt2) {
                int row = wn * 32 + nt2 * 16 + lrow;
                uint32_t ch = (uint32_t)(ks * 2 + lsel);
                uint32_t bd = bb + (uint32_t)row * 128u + ((ch ^ (uint32_t)(row & 7)) * 16u);
                uint32_t r0, r1, r2, r3;
                ldsm_x4(r0, r1, r2, r3, bd);
                b[nt2 * 2 + 0][0] = r0; b[nt2 * 2 + 1][0] = r1;
                b[nt2 * 2 + 0][1] = r2; b[nt2 * 2 + 1][1] = r3;
            }
            #pragma unroll
            for (int mt = 0; mt < 4; ++mt)
                #pragma unroll
                for (int nt = 0; nt < 4; ++nt)
                    mma16816(acc[mt][nt][0], acc[mt][nt][1],
                             acc[mt][nt][2], acc[mt][nt][3],
                             a[mt][0], a[mt][1], a[mt][2], a[mt][3],
                             b[nt][0], b[nt][1]);
        }
        __syncthreads();
    }
    cp_wait<0>();

    float* __restrict__ C = args.C;
    const int rbase = tileM * 128 + wm * 64 + (lane >> 2);
    const int cbase = tileN * 128 + wn * 32 + (lane & 3) * 2;
    #pragma unroll
    for (int mt = 0; mt < 4; ++mt) {
        #pragma unroll
        for (int nt = 0; nt < 4; ++nt) {
            int r0 = rbase + mt * 16;
            int cc = cbase + nt * 8;
            *reinterpret_cast<float2*>(C + (size_t)r0 * ND + cc) =
                make_float2(acc[mt][nt][0], acc[mt][nt][1]);
            *reinterpret_cast<float2*>(C + (size_t)(r0 + 8) * ND + cc) =
                make_float2(acc[mt][nt][2], acc[mt][nt][3]);
        }
    }
}

// ---------------- fp32 -> bf16 2-split ----------------
__global__ void __launch_bounds__(256) split2_kernel(
    const float4* __restrict__ in, uint2* __restrict__ o0,
    uint2* __restrict__ o1, int n4)
{
    int i = blockIdx.x * blockDim.x + threadIdx.x;
    if (i >= n4) return;
    float4 v = in[i];
    float f[4] = {v.x, v.y, v.z, v.w};
    unsigned short a[4], b[4];
    #pragma unroll
    for (int j = 0; j < 4; ++j) {
        __nv_bfloat16 h0 = __float2bfloat16_rn(f[j]);
        float r = f[j] - __bfloat162float(h0);
        __nv_bfloat16 h1 = __float2bfloat16_rn(r);
        a[j] = __bfloat16_as_ushort(h0);
        b[j] = __bfloat16_as_ushort(h1);
    }
    o0[i] = make_uint2((uint32_t)a[0] | ((uint32_t)a[1] << 16),
                       (uint32_t)a[2] | ((uint32_t)a[3] << 16));
    o1[i] = make_uint2((uint32_t)b[0] | ((uint32_t)b[1] << 16),
                       (uint32_t)b[2] | ((uint32_t)b[3] << 16));
}

// ---------------- zero flag counter ----------------
__global__ void zero_counter() { g_flag_count = 0; }

// ---------------- LIF on h_fast + near-threshold flagging ------------------
#define MARGIN 1e-4f

__global__ void __launch_bounds__(256) lif_flag_kernel(
    const float4* __restrict__ h, uint2* __restrict__ s)
{
    const int n4 = NCHAN / 4;
    int i = blockIdx.x * blockDim.x + threadIdx.x;
    if (i >= n4) return;
    float v[4] = {0.f, 0.f, 0.f, 0.f};
    bool risky[4] = {false, false, false, false};
    #pragma unroll
    for (int t = 0; t < 4; ++t) {
        float4 x = h[(size_t)t * n4 + i];
        float xf[4] = {x.x, x.y, x.z, x.w};
        unsigned short sp[4];
        #pragma unroll
        for (int j = 0; j < 4; ++j) {
            v[j] = v[j] + (xf[j] - v[j]) / 2.0f;
            risky[j] |= (fabsf(v[j] - 1.0f) < MARGIN);
            bool fire = (v[j] >= 1.0f);
            sp[j] = fire ? (unsigned short)0x3F80 : (unsigned short)0;
            if (fire) v[j] = 0.0f;
        }
        s[(size_t)t * n4 + i] =
            make_uint2((uint32_t)sp[0] | ((uint32_t)sp[1] << 16),
                       (uint32_t)sp[2] | ((uint32_t)sp[3] << 16));
    }
    #pragma unroll
    for (int j = 0; j < 4; ++j) {
        if (risky[j]) {
            int slot = atomicAdd(&g_flag_count, 1);
            if (slot < FLAG_CAP) g_flags[slot] = i * 4 + j;
        }
    }
}

// ---------------- exact fix-up: bit-identical sequential fp32 dot ----------
__global__ void __launch_bounds__(128) fixup_kernel(
    const float* __restrict__ x, const float* __restrict__ W1,
    __nv_bfloat16* __restrict__ s)
{
    int count = g_flag_count;
    if (count > FLAG_CAP) count = FLAG_CAP;
    for (int j = blockIdx.x * blockDim.x + threadIdx.x; j < count;
         j += gridDim.x * blockDim.x) {
        const int idx = g_flags[j];
        const int bn  = idx >> 9;          // row within [B*N]
        const int c   = idx & 511;         // output channel
        const float4* w = reinterpret_cast<const float4*>(W1 + (size_t)c * KD);
        float v = 0.0f;
        #pragma unroll 1
        for (int t = 0; t < 4; ++t) {
            const float4* xr = reinterpret_cast<const float4*>(
                x + ((size_t)t * MPERT + bn) * KD);
            float acc = 0.0f;
            // single accumulator, ascending k: bit-identical to reference GEMM
            for (int k4 = 0; k4 < KD / 4; ++k4) {
                float4 xv = xr[k4];
                float4 wv = w[k4];
                acc = fmaf(xv.x, wv.x, acc);
                acc = fmaf(xv.y, wv.y, acc);
                acc = fmaf(xv.z, wv.z, acc);
                acc = fmaf(xv.w, wv.w, acc);
            }
            v = v + (acc - v) / 2.0f;
            bool fire = (v >= 1.0f);
            s[(size_t)t * NCHAN + idx] =
                __ushort_as_bfloat16(fire ? (unsigned short)0x3F80 : (unsigned short)0);
            if (fire) v = 0.0f;
        }
    }
}

// ---------------- launch ----------------
extern "C" void kernel_launch(void* const* d_in, const int* in_sizes, int n_in,
                              void* d_out, int out_size)
{
    const float* x  = (const float*)d_in[0];
    const float* W1 = (const float*)d_in[1];
    const float* W2 = (const float*)d_in[2];
    float* out = (float*)d_out;

    __nv_bfloat16 *x0, *x1, *w10, *w11, *w20, *w21, *s;
    float* h;
    cudaGetSymbolAddress((void**)&x0,  g_x0);
    cudaGetSymbolAddress((void**)&x1,  g_x1);
    cudaGetSymbolAddress((void**)&w10, g_w10);
    cudaGetSymbolAddress((void**)&w11, g_w11);
    cudaGetSymbolAddress((void**)&w20, g_w20);
    cudaGetSymbolAddress((void**)&w21, g_w21);
    cudaGetSymbolAddress((void**)&h,   g_h);
    cudaGetSymbolAddress((void**)&s,   g_s);

    cudaFuncSetAttribute(hmma_gemm, cudaFuncAttributeMaxDynamicSharedMemorySize, SMEM_DYN);

    split2_kernel<<<(MTOT * KD / 4) / 256, 256>>>(
        (const float4*)x, (uint2*)x0, (uint2*)x1, MTOT * KD / 4);
    split2_kernel<<<(KD * ND / 4) / 256, 256>>>(
        (const float4*)W1, (uint2*)w10, (uint2*)w11, KD * ND / 4);
    split2_kernel<<<(KD * ND / 4) / 256, 256>>>(
        (const float4*)W2, (uint2*)w20, (uint2*)w21, KD * ND / 4);

    // GEMM1: h_fast = x @ W1^T via 4 bf16 products (A-grouped for L2 reuse)
    GemmArgs g1;
    g1.A[0] = x0; g1.B[0] = w10;
    g1.A[1] = x0; g1.B[1] = w11;
    g1.A[2] = x1; g1.B[2] = w10;
    g1.A[3] = x1; g1.B[3] = w11;
    g1.C = h; g1.npairs = 4;
    hmma_gemm<<<dim3(4, 256), 256, SMEM_DYN>>>(g1);

    zero_counter<<<1, 1>>>();
    lif_flag_kernel<<<(NCHAN / 4) / 256, 256>>>((const float4*)h, (uint2*)s);
    fixup_kernel<<<256, 128>>>(x, W1, s);

    // GEMM2: out = s @ W2^T via 2 bf16 products (spikes exact in bf16)
    GemmArgs g2;
    g2.A[0] = s; g2.B[0] = w20;
    g2.A[1] = s; g2.B[1] = w21;
    g2.A[2] = s; g2.B[2] = w20;   // unused
    g2.A[3] = s; g2.B[3] = w21;
    g2.C = out; g2.npairs = 2;
    hmma_gemm<<<dim3(4, 256), 256, SMEM_DYN>>>(g2);
}

// round 5
// speedup vs baseline: 1.5951x; 1.1043x over previous
#include <cuda_runtime.h>
#include <cuda_bf16.h>
#include <cstdint>

// Shapes (fixed): x [4,8,1024,512] -> M=32768 rows, K=512; W1,W2 [512,512].
#define MTOT  32768
#define MPERT 8192
#define KD    512
#define ND    512
#define NCHAN (MPERT * ND)
#define FLAG_CAP 2097152

// ---------------- scratch (no cudaMalloc allowed) ----------------
__device__ __align__(16) __nv_bfloat16 g_x0[(size_t)MTOT * KD];
__device__ __align__(16) __nv_bfloat16 g_x1[(size_t)MTOT * KD];
__device__ __align__(16) __nv_bfloat16 g_w10[KD * ND];
__device__ __align__(16) __nv_bfloat16 g_w11[KD * ND];
__device__ __align__(16) __nv_bfloat16 g_w20[KD * ND];
__device__ __align__(16) __nv_bfloat16 g_w21[KD * ND];
__device__ __align__(16) float         g_h[(size_t)MTOT * ND];
__device__ __align__(16) __nv_bfloat16 g_s[(size_t)MTOT * ND];
__device__ int g_flags[FLAG_CAP];
__device__ int g_flag_count;

// ---------------- base-target PTX helpers (sm_80-era only) -----------------
__device__ __forceinline__ uint32_t smem_u32(const void* p) {
    uint32_t a;
    asm("{ .reg .u64 t; cvta.to.shared.u64 t, %1; cvt.u32.u64 %0, t; }"
        : "=r"(a) : "l"(p));
    return a;
}
__device__ __forceinline__ void cp_async16(uint32_t dst, const void* src) {
    asm volatile("cp.async.cg.shared.global [%0], [%1], 16;"
                 :: "r"(dst), "l"(src) : "memory");
}
__device__ __forceinline__ void cp_commit() {
    asm volatile("cp.async.commit_group;" ::: "memory");
}
template <int N>
__device__ __forceinline__ void cp_wait() {
    asm volatile("cp.async.wait_group %0;" :: "n"(N) : "memory");
}
__device__ __forceinline__ void ldsm_x4(uint32_t& r0, uint32_t& r1,
                                        uint32_t& r2, uint32_t& r3, uint32_t a) {
    asm volatile("ldmatrix.sync.aligned.m8n8.x4.shared.b16 {%0,%1,%2,%3}, [%4];"
                 : "=r"(r0), "=r"(r1), "=r"(r2), "=r"(r3) : "r"(a));
}
__device__ __forceinline__ void mma16816(float& c0, float& c1, float& c2, float& c3,
                                         uint32_t a0, uint32_t a1, uint32_t a2, uint32_t a3,
                                         uint32_t b0, uint32_t b1) {
    asm volatile(
        "mma.sync.aligned.m16n8k16.row.col.f32.bf16.bf16.f32 "
        "{%0,%1,%2,%3}, {%4,%5,%6,%7}, {%8,%9}, {%0,%1,%2,%3};"
        : "+f"(c0), "+f"(c1), "+f"(c2), "+f"(c3)
        : "r"(a0), "r"(a1), "r"(a2), "r"(a3), "r"(b0), "r"(b1));
}

// ---------------- bf16 HMMA GEMM: C[M,512] = sum_p A_p @ B_p^T --------------
// CTA 128x128, BK=64, 8 warps @ 64x32, 3-stage cp.async, B-frag double buffer.
struct GemmArgs {
    const __nv_bfloat16* A[4];
    const __nv_bfloat16* B[4];
    float* C;
    int npairs;
};

#define STAGE_BYTES 32768
#define NSTAGE 3
#define SMEM_DYN (STAGE_BYTES * NSTAGE)   // 96 KB

__global__ void __launch_bounds__(256, 2) hmma_gemm(GemmArgs args)
{
    extern __shared__ char dynsmem[];
    const uint32_t sb = smem_u32(dynsmem);

    const int tid   = threadIdx.x;
    const int lane  = tid & 31;
    const int warp  = tid >> 5;
    const int wm    = warp >> 2;
    const int wn    = warp & 3;
    const int tileN = blockIdx.x;          // fast dim -> A tile L2 reuse
    const int tileM = blockIdx.y;

    const int niters = args.npairs * 8;

    const int ldRow = tid >> 1;
    const int ldC0  = (tid & 1) * 4;
    const int lrow  = lane & 15;
    const int lsel  = lane >> 4;

    float acc[4][4][4];
    #pragma unroll
    for (int i = 0; i < 4; ++i)
        #pragma unroll
        for (int j = 0; j < 4; ++j)
            #pragma unroll
            for (int q = 0; q < 4; ++q) acc[i][j][q] = 0.f;

    auto load_stage = [&](int it) {
        const int pair = it >> 3;
        const int k0   = (it & 7) * 64;
        const __nv_bfloat16* Ap = args.A[pair] + (size_t)tileM * 128 * KD + k0;
        const __nv_bfloat16* Bp = args.B[pair] + (size_t)tileN * 128 * KD + k0;
        const uint32_t ab = sb + (it % NSTAGE) * STAGE_BYTES;
        const uint32_t bb = ab + 16384;
        const uint32_t swrow = (uint32_t)(ldRow & 7);
        #pragma unroll
        for (int c = 0; c < 4; ++c) {
            uint32_t ch = (uint32_t)(ldC0 + c);
            uint32_t sw = (ch ^ swrow) * 16u + (uint32_t)ldRow * 128u;
            cp_async16(ab + sw, Ap + (size_t)ldRow * KD + ch * 8);
            cp_async16(bb + sw, Bp + (size_t)ldRow * KD + ch * 8);
        }
        cp_commit();
    };

    load_stage(0);
    load_stage(1);

    uint32_t a[4][4];       // A frags for current ks
    uint32_t b2[2][4][2];   // B frags, double buffered across ks

    auto load_a = [&](uint32_t ab, int ks) {
        #pragma unroll
        for (int mt = 0; mt < 4; ++mt) {
            int row = wm * 64 + mt * 16 + lrow;
            uint32_t ch = (uint32_t)(ks * 2 + lsel);
            uint32_t ad = ab + (uint32_t)row * 128u + ((ch ^ (uint32_t)(row & 7)) * 16u);
            ldsm_x4(a[mt][0], a[mt][1], a[mt][2], a[mt][3], ad);
        }
    };
    auto load_b = [&](uint32_t bb, int ks, int pb) {
        #pragma unroll
        for (int nt2 = 0; nt2 < 2; ++nt2) {
            int row = wn * 32 + nt2 * 16 + lrow;
            uint32_t ch = (uint32_t)(ks * 2 + lsel);
            uint32_t bd = bb + (uint32_t)row * 128u + ((ch ^ (uint32_t)(row & 7)) * 16u);
            uint32_t r0, r1, r2, r3;
            ldsm_x4(r0, r1, r2, r3, bd);
            b2[pb][nt2 * 2 + 0][0] = r0; b2[pb][nt2 * 2 + 1][0] = r1;
            b2[pb][nt2 * 2 + 0][1] = r2; b2[pb][nt2 * 2 + 1][1] = r3;
        }
    };

    for (int it = 0; it < niters; ++it) {
        if (it + 2 < niters) load_stage(it + 2);
        else cp_commit();                 // keep group count uniform
        cp_wait<2>();
        __syncthreads();

        const uint32_t ab = sb + (it % NSTAGE) * STAGE_BYTES;
        const uint32_t bb = ab + 16384;

        load_b(bb, 0, 0);
        load_a(ab, 0);

        #pragma unroll
        for (int ks = 0; ks < 4; ++ks) {
            if (ks < 3) load_b(bb, ks + 1, (ks + 1) & 1);   // hide behind MMAs
            #pragma unroll
            for (int mt = 0; mt < 4; ++mt)
                #pragma unroll
                for (int nt = 0; nt < 4; ++nt)
                    mma16816(acc[mt][nt][0], acc[mt][nt][1],
                             acc[mt][nt][2], acc[mt][nt][3],
                             a[mt][0], a[mt][1], a[mt][2], a[mt][3],
                             b2[ks & 1][nt][0], b2[ks & 1][nt][1]);
            if (ks < 3) load_a(ab, ks + 1);
        }
        __syncthreads();
    }
    cp_wait<0>();

    float* __restrict__ C = args.C;
    const int rbase = tileM * 128 + wm * 64 + (lane >> 2);
    const int cbase = tileN * 128 + wn * 32 + (lane & 3) * 2;
    #pragma unroll
    for (int mt = 0; mt < 4; ++mt) {
        #pragma unroll
        for (int nt = 0; nt < 4; ++nt) {
            int r0 = rbase + mt * 16;
            int cc = cbase + nt * 8;
            *reinterpret_cast<float2*>(C + (size_t)r0 * ND + cc) =
                make_float2(acc[mt][nt][0], acc[mt][nt][1]);
            *reinterpret_cast<float2*>(C + (size_t)(r0 + 8) * ND + cc) =
                make_float2(acc[mt][nt][2], acc[mt][nt][3]);
        }
    }
}

// ---------------- fp32 -> bf16 2-split ----------------
__global__ void __launch_bounds__(256) split2_kernel(
    const float4* __restrict__ in, uint2* __restrict__ o0,
    uint2* __restrict__ o1, int n4)
{
    int i = blockIdx.x * blockDim.x + threadIdx.x;
    if (i >= n4) return;
    float4 v = in[i];
    float f[4] = {v.x, v.y, v.z, v.w};
    unsigned short a[4], b[4];
    #pragma unroll
    for (int j = 0; j < 4; ++j) {
        __nv_bfloat16 h0 = __float2bfloat16_rn(f[j]);
        float r = f[j] - __bfloat162float(h0);
        __nv_bfloat16 h1 = __float2bfloat16_rn(r);
        a[j] = __bfloat16_as_ushort(h0);
        b[j] = __bfloat16_as_ushort(h1);
    }
    o0[i] = make_uint2((uint32_t)a[0] | ((uint32_t)a[1] << 16),
                       (uint32_t)a[2] | ((uint32_t)a[3] << 16));
    o1[i] = make_uint2((uint32_t)b[0] | ((uint32_t)b[1] << 16),
                       (uint32_t)b[2] | ((uint32_t)b[3] << 16));
}

__global__ void zero_counter() { g_flag_count = 0; }

// ---------------- LIF on h_fast + near-threshold flagging ------------------
#define MARGIN 1e-4f

__global__ void __launch_bounds__(256) lif_flag_kernel(
    const float4* __restrict__ h, uint2* __restrict__ s)
{
    const int n4 = NCHAN / 4;
    int i = blockIdx.x * blockDim.x + threadIdx.x;
    if (i >= n4) return;
    float v[4] = {0.f, 0.f, 0.f, 0.f};
    bool risky[4] = {false, false, false, false};
    #pragma unroll
    for (int t = 0; t < 4; ++t) {
        float4 x = h[(size_t)t * n4 + i];
        float xf[4] = {x.x, x.y, x.z, x.w};
        unsigned short sp[4];
        #pragma unroll
        for (int j = 0; j < 4; ++j) {
            v[j] = v[j] + (xf[j] - v[j]) / 2.0f;
            risky[j] |= (fabsf(v[j] - 1.0f) < MARGIN);
            bool fire = (v[j] >= 1.0f);
            sp[j] = fire ? (unsigned short)0x3F80 : (unsigned short)0;
            if (fire) v[j] = 0.0f;
        }
        s[(size_t)t * n4 + i] =
            make_uint2((uint32_t)sp[0] | ((uint32_t)sp[1] << 16),
                       (uint32_t)sp[2] | ((uint32_t)sp[3] << 16));
    }
    #pragma unroll
    for (int j = 0; j < 4; ++j) {
        if (risky[j]) {
            int slot = atomicAdd(&g_flag_count, 1);
            if (slot < FLAG_CAP) g_flags[slot] = i * 4 + j;
        }
    }
}

// ---------------- exact fix-up: bit-identical sequential fp32 dot ----------
__global__ void __launch_bounds__(128) fixup_kernel(
    const float* __restrict__ x, const float* __restrict__ W1,
    __nv_bfloat16* __restrict__ s)
{
    int count = g_flag_count;
    if (count > FLAG_CAP) count = FLAG_CAP;
    for (int j = blockIdx.x * blockDim.x + threadIdx.x; j < count;
         j += gridDim.x * blockDim.x) {
        const int idx = g_flags[j];
        const int bn  = idx >> 9;
        const int c   = idx & 511;
        const float4* w = reinterpret_cast<const float4*>(W1 + (size_t)c * KD);
        float v = 0.0f;
        #pragma unroll 1
        for (int t = 0; t < 4; ++t) {
            const float4* xr = reinterpret_cast<const float4*>(
                x + ((size_t)t * MPERT + bn) * KD);
            float acc = 0.0f;
            for (int k4 = 0; k4 < KD / 4; ++k4) {
                float4 xv = xr[k4];
                float4 wv = w[k4];
                acc = fmaf(xv.x, wv.x, acc);
                acc = fmaf(xv.y, wv.y, acc);
                acc = fmaf(xv.z, wv.z, acc);
                acc = fmaf(xv.w, wv.w, acc);
            }
            v = v + (acc - v) / 2.0f;
            bool fire = (v >= 1.0f);
            s[(size_t)t * NCHAN + idx] =
                __ushort_as_bfloat16(fire ? (unsigned short)0x3F80 : (unsigned short)0);
            if (fire) v = 0.0f;
        }
    }
}

// ---------------- launch ----------------
extern "C" void kernel_launch(void* const* d_in, const int* in_sizes, int n_in,
                              void* d_out, int out_size)
{
    const float* x  = (const float*)d_in[0];
    const float* W1 = (const float*)d_in[1];
    const float* W2 = (const float*)d_in[2];
    float* out = (float*)d_out;

    __nv_bfloat16 *x0, *x1, *w10, *w11, *w20, *w21, *s;
    float* h;
    cudaGetSymbolAddress((void**)&x0,  g_x0);
    cudaGetSymbolAddress((void**)&x1,  g_x1);
    cudaGetSymbolAddress((void**)&w10, g_w10);
    cudaGetSymbolAddress((void**)&w11, g_w11);
    cudaGetSymbolAddress((void**)&w20, g_w20);
    cudaGetSymbolAddress((void**)&w21, g_w21);
    cudaGetSymbolAddress((void**)&h,   g_h);
    cudaGetSymbolAddress((void**)&s,   g_s);

    cudaFuncSetAttribute(hmma_gemm, cudaFuncAttributeMaxDynamicSharedMemorySize, SMEM_DYN);

    zero_counter<<<1, 1>>>();
    split2_kernel<<<(MTOT * KD / 4) / 256, 256>>>(
        (const float4*)x, (uint2*)x0, (uint2*)x1, MTOT * KD / 4);
    split2_kernel<<<(KD * ND / 4) / 256, 256>>>(
        (const float4*)W1, (uint2*)w10, (uint2*)w11, KD * ND / 4);
    split2_kernel<<<(KD * ND / 4) / 256, 256>>>(
        (const float4*)W2, (uint2*)w20, (uint2*)w21, KD * ND / 4);

    // GEMM1: h_fast = x @ W1^T via 3 bf16 products (x1*w11 term dropped:
    // ~2^-18 error, 26x below flag margin; fixup is exact regardless)
    GemmArgs g1;
    g1.A[0] = x0; g1.B[0] = w10;
    g1.A[1] = x0; g1.B[1] = w11;
    g1.A[2] = x1; g1.B[2] = w10;
    g1.A[3] = x1; g1.B[3] = w11;   // unused
    g1.C = h; g1.npairs = 3;
    hmma_gemm<<<dim3(4, 256), 256, SMEM_DYN>>>(g1);

    lif_flag_kernel<<<(NCHAN / 4) / 256, 256>>>((const float4*)h, (uint2*)s);
    fixup_kernel<<<256, 128>>>(x, W1, s);

    // GEMM2: out = s @ W2^T via 2 bf16 products (spikes exact in bf16)
    GemmArgs g2;
    g2.A[0] = s; g2.B[0] = w20;
    g2.A[1] = s; g2.B[1] = w21;
    g2.A[2] = s; g2.B[2] = w20;   // unused
    g2.A[3] = s; g2.B[3] = w21;
    g2.C = out; g2.npairs = 2;
    hmma_gemm<<<dim3(4, 256), 256, SMEM_DYN>>>(g2);
}